// round 2
// baseline (speedup 1.0000x reference)
#include <cuda_runtime.h>
#include <math.h>

// Problem constants (fixed shapes per reference)
#define BATCH 4
#define SEQ   2048
#define DIM   1024   // input size
#define EMB   1024   // qk/out size

// Tiling
#define BM 128
#define BN 128
#define BK 16
#define TM 8
#define TN 8
// threads per block = (BM/TM) * (BN/TN) = 256

// Scratch (device globals — no allocation allowed)
__device__ float g_Q[(size_t)BATCH * SEQ * EMB];
__device__ float g_K[(size_t)BATCH * SEQ * EMB];
__device__ float g_V[(size_t)BATCH * SEQ * EMB];
__device__ float g_S[(size_t)BATCH * SEQ * SEQ];

// C[M,N] = alpha * A[M,K] @ op(B) + bias
// TRANSB=true : op(B) = B^T with B stored [N,K] row-major (torch Linear / Q@K^T)
// TRANSB=false: op(B) = B   with B stored [K,N] row-major (attn @ V)
template <bool TRANSB>
__global__ __launch_bounds__(256, 2) void sgemm_kernel(
    const float* __restrict__ A, const float* __restrict__ Bm,
    const float* __restrict__ bias, float* __restrict__ C,
    int M, int N, int K, float alpha,
    long long sA, long long sB, long long sC)
{
    A  += (long long)blockIdx.z * sA;
    Bm += (long long)blockIdx.z * sB;
    C  += (long long)blockIdx.z * sC;

    __shared__ float As[BK][BM];
    __shared__ float Bs[BK][BN];

    const int tid = threadIdx.x;
    const int tx = tid & 15;   // 0..15 -> N direction
    const int ty = tid >> 4;   // 0..15 -> M direction

    const int rowBase = blockIdx.y * BM;
    const int colBase = blockIdx.x * BN;

    float acc[TM][TN];
#pragma unroll
    for (int i = 0; i < TM; i++)
#pragma unroll
        for (int j = 0; j < TN; j++) acc[i][j] = 0.0f;

    for (int k0 = 0; k0 < K; k0 += BK) {
        // ---- load A tile [BM x BK], store transposed As[k][m] ----
        {
            const int r = tid >> 2;            // 0..63
            const int c = (tid & 3) << 2;      // 0,4,8,12
#pragma unroll
            for (int i = 0; i < 2; i++) {
                const int rr = r + i * 64;
                float4 v = *(const float4*)&A[(long long)(rowBase + rr) * K + k0 + c];
                As[c + 0][rr] = v.x;
                As[c + 1][rr] = v.y;
                As[c + 2][rr] = v.z;
                As[c + 3][rr] = v.w;
            }
        }
        // ---- load B tile ----
        if (TRANSB) {
            // B stored [N,K]; tile is BN x BK; store transposed Bs[k][n]
            const int r = tid >> 2;
            const int c = (tid & 3) << 2;
#pragma unroll
            for (int i = 0; i < 2; i++) {
                const int rr = r + i * 64;
                float4 v = *(const float4*)&Bm[(long long)(colBase + rr) * K + k0 + c];
                Bs[c + 0][rr] = v.x;
                Bs[c + 1][rr] = v.y;
                Bs[c + 2][rr] = v.z;
                Bs[c + 3][rr] = v.w;
            }
        } else {
            // B stored [K,N]; tile is BK x BN; direct copy (coalesced)
            const int r = tid >> 5;            // 0..7
            const int c = (tid & 31) << 2;     // 0..124 step 4
#pragma unroll
            for (int i = 0; i < 2; i++) {
                const int rr = r + i * 8;
                float4 v = *(const float4*)&Bm[(long long)(k0 + rr) * N + colBase + c];
                *(float4*)&Bs[rr][c] = v;
            }
        }
        __syncthreads();

#pragma unroll
        for (int kk = 0; kk < BK; kk++) {
            float ra[TM], rb[TN];
#pragma unroll
            for (int i = 0; i < TM; i++) ra[i] = As[kk][ty * TM + i];
#pragma unroll
            for (int j = 0; j < TN; j++) rb[j] = Bs[kk][tx * TN + j];
#pragma unroll
            for (int i = 0; i < TM; i++)
#pragma unroll
                for (int j = 0; j < TN; j++)
                    acc[i][j] = fmaf(ra[i], rb[j], acc[i][j]);
        }
        __syncthreads();
    }

    // ---- epilogue ----
#pragma unroll
    for (int i = 0; i < TM; i++) {
        const long long r = rowBase + ty * TM + i;
#pragma unroll
        for (int j = 0; j < TN; j += 4) {
            const int c = colBase + tx * TN + j;
            float4 v;
            v.x = alpha * acc[i][j + 0];
            v.y = alpha * acc[i][j + 1];
            v.z = alpha * acc[i][j + 2];
            v.w = alpha * acc[i][j + 3];
            if (bias != nullptr) {
                v.x += bias[c + 0];
                v.y += bias[c + 1];
                v.z += bias[c + 2];
                v.w += bias[c + 3];
            }
            *(float4*)&C[r * N + c] = v;
        }
    }
}

// Row softmax, in place. One block per row; L must be 2048; 256 threads.
__global__ __launch_bounds__(256) void softmax_kernel(float* __restrict__ S, int L)
{
    float* row = S + (long long)blockIdx.x * L;
    const int tid = threadIdx.x;

    float v[8];
    float m = -INFINITY;
#pragma unroll
    for (int i = 0; i < 8; i++) {
        v[i] = row[tid + i * 256];
        m = fmaxf(m, v[i]);
    }

    __shared__ float red[256];
    red[tid] = m;
    __syncthreads();
#pragma unroll
    for (int s = 128; s > 0; s >>= 1) {
        if (tid < s) red[tid] = fmaxf(red[tid], red[tid + s]);
        __syncthreads();
    }
    m = red[0];
    __syncthreads();

    float sum = 0.0f;
#pragma unroll
    for (int i = 0; i < 8; i++) {
        v[i] = __expf(v[i] - m);
        sum += v[i];
    }
    red[tid] = sum;
    __syncthreads();
#pragma unroll
    for (int s = 128; s > 0; s >>= 1) {
        if (tid < s) red[tid] += red[tid + s];
        __syncthreads();
    }
    const float inv = 1.0f / red[0];
#pragma unroll
    for (int i = 0; i < 8; i++)
        row[tid + i * 256] = v[i] * inv;
}

extern "C" void kernel_launch(void* const* d_in, const int* in_sizes, int n_in,
                              void* d_out, int out_size)
{
    const float* x  = (const float*)d_in[0];
    const float* Wq = (const float*)d_in[1];
    const float* bq = (const float*)d_in[2];
    const float* Wk = (const float*)d_in[3];
    const float* bk = (const float*)d_in[4];
    const float* Wv = (const float*)d_in[5];
    const float* bv = (const float*)d_in[6];
    float* out = (float*)d_out;

    float *Q, *K_, *V, *Sc;
    cudaGetSymbolAddress((void**)&Q,  g_Q);
    cudaGetSymbolAddress((void**)&K_, g_K);
    cudaGetSymbolAddress((void**)&V,  g_V);
    cudaGetSymbolAddress((void**)&Sc, g_S);

    const int Mq = BATCH * SEQ;  // 8192 rows for projections
    const dim3 blk(256);

    // QKV projections: [8192,1024] @ W^T[1024,1024] + b
    {
        dim3 grid(EMB / BN, Mq / BM, 1);
        sgemm_kernel<true><<<grid, blk>>>(x, Wq, bq, Q,  Mq, EMB, DIM, 1.0f, 0, 0, 0);
        sgemm_kernel<true><<<grid, blk>>>(x, Wk, bk, K_, Mq, EMB, DIM, 1.0f, 0, 0, 0);
        sgemm_kernel<true><<<grid, blk>>>(x, Wv, bv, V,  Mq, EMB, DIM, 1.0f, 0, 0, 0);
    }

    // scores = Q @ K^T / sqrt(1024), batched over z
    {
        dim3 grid(SEQ / BN, SEQ / BM, BATCH);
        sgemm_kernel<true><<<grid, blk>>>(
            Q, K_, nullptr, Sc, SEQ, SEQ, EMB, 0.03125f,
            (long long)SEQ * EMB, (long long)SEQ * EMB, (long long)SEQ * SEQ);
    }

    // softmax rows
    softmax_kernel<<<BATCH * SEQ, 256>>>(Sc, SEQ);

    // out = attn @ V, batched over z
    {
        dim3 grid(EMB / BN, SEQ / BM, BATCH);
        sgemm_kernel<false><<<grid, blk>>>(
            Sc, V, nullptr, out, SEQ, EMB, SEQ, 1.0f,
            (long long)SEQ * SEQ, (long long)SEQ * EMB, (long long)SEQ * EMB);
    }
}

// round 4
// speedup vs baseline: 3.7450x; 3.7450x over previous
#include <cuda_runtime.h>
#include <math.h>
#include <cstdint>

// Problem constants
#define BATCH 4
#define SEQ   2048
#define DIM   1024
#define EMB   1024

// Tiling
#define BM 128
#define BN 128
#define BK 32
// 256 threads = 8 warps, 2 (M) x 4 (N); warp tile 64x32

// Scratch (device globals — no allocation allowed)
__device__ float g_Q[(size_t)BATCH * SEQ * EMB];
__device__ float g_K[(size_t)BATCH * SEQ * EMB];
__device__ float g_V[(size_t)BATCH * SEQ * EMB];
__device__ float g_S[(size_t)BATCH * SEQ * SEQ];   // scores; front 32MB doubles as rounded-x
__device__ float g_Wr[3][(size_t)EMB * DIM];       // rounded weights

// ---------------- helpers ----------------
__device__ __forceinline__ float round_tf32(float x) {
    uint32_t u;
    asm("cvt.rna.tf32.f32 %0, %1;" : "=r"(u) : "f"(x));
    return __uint_as_float(u);
}
__device__ __forceinline__ uint32_t smem_u32(const void* p) {
    uint32_t a;
    asm("{ .reg .u64 t; cvta.to.shared.u64 t, %1; cvt.u32.u64 %0, t; }" : "=r"(a) : "l"(p));
    return a;
}
#define CP_ASYNC16(sm, gp) asm volatile("cp.async.cg.shared.global [%0], [%1], 16;" :: "r"(sm), "l"(gp))
#define CP_COMMIT()        asm volatile("cp.async.commit_group;" ::: "memory")
#define CP_WAIT(n)         asm volatile("cp.async.wait_group %0;" :: "n"(n) : "memory")

__device__ __forceinline__ void mma_tf32(float c[4], const uint32_t a[4], const uint32_t b[2]) {
    asm volatile(
        "mma.sync.aligned.m16n8k8.row.col.f32.tf32.tf32.f32 "
        "{%0,%1,%2,%3}, {%4,%5,%6,%7}, {%8,%9}, {%0,%1,%2,%3};"
        : "+f"(c[0]), "+f"(c[1]), "+f"(c[2]), "+f"(c[3])
        : "r"(a[0]), "r"(a[1]), "r"(a[2]), "r"(a[3]), "r"(b[0]), "r"(b[1]));
}

// smem strides (floats)
#define ALD 36     // BK+4 : A row stride
#define BLDT 36    // BK+4 : B row stride (TRANSB, [BN][.])
#define BLDN 136   // BN+8 : B row stride (NN, [BK][.])
#define A_STAGE_B (BM * ALD * 4)              // 18432
#define B_STAGE_B (BM * BLDT * 4)             // 18432 (>= 32*136*4 = 17408)
#define SMEM_SIZE (2 * A_STAGE_B + 2 * B_STAGE_B)  // 73728

// ---------------- mma.sync tf32 GEMM ----------------
// C[M,N] = alpha * A[M,K] @ op(B) + bias
// TRANSB: B stored [N,K] (Linear weights / K^T). Else B stored [K,N] (attn@V).
// ROUND: round outputs to tf32 (operands of downstream MMAs).
template <bool TRANSB, bool ROUND>
__global__ __launch_bounds__(256, 2) void mma_gemm(
    const float* __restrict__ A, const float* __restrict__ Bm,
    const float* __restrict__ bias, float* __restrict__ C,
    int M, int N, int K, float alpha,
    long long sA, long long sB, long long sC)
{
    extern __shared__ char smem[];
    uint32_t* sA32 = (uint32_t*)smem;
    uint32_t* sB32 = (uint32_t*)(smem + 2 * A_STAGE_B);
    const uint32_t smA = smem_u32(smem);
    const uint32_t smB = smA + 2 * A_STAGE_B;

    A  += (long long)blockIdx.z * sA;
    Bm += (long long)blockIdx.z * sB;
    C  += (long long)blockIdx.z * sC;
    const int rowBase = blockIdx.y * BM;
    const int colBase = blockIdx.x * BN;

    const int tid = threadIdx.x;
    const int wid = tid >> 5, lane = tid & 31;
    const int wm = wid >> 2;           // 0..1  (M)
    const int wn = wid & 3;            // 0..3  (N)
    const int gid = lane >> 2;         // 0..7
    const int tig = lane & 3;          // 0..3

    float acc[4][4][4];
#pragma unroll
    for (int i = 0; i < 4; i++)
#pragma unroll
        for (int j = 0; j < 4; j++)
#pragma unroll
            for (int t = 0; t < 4; t++) acc[i][j][t] = 0.0f;

    // ---- async tile loaders ----
    auto load_tiles = [&](int k0, int buf) {
        // A tile: 128 rows x 32 floats -> [BM][ALD], 16B chunks
#pragma unroll
        for (int jj = 0; jj < 4; jj++) {
            const int idx = tid + jj * 256;        // 0..1023
            const int r = idx >> 3, c = idx & 7;   // c: float4 chunk in k
            const float* gp = &A[(long long)(rowBase + r) * K + k0 + c * 4];
            CP_ASYNC16(smA + buf * A_STAGE_B + (r * ALD + c * 4) * 4, gp);
        }
        if (TRANSB) {
#pragma unroll
            for (int jj = 0; jj < 4; jj++) {
                const int idx = tid + jj * 256;
                const int r = idx >> 3, c = idx & 7;
                const float* gp = &Bm[(long long)(colBase + r) * K + k0 + c * 4];
                CP_ASYNC16(smB + buf * B_STAGE_B + (r * BLDT + c * 4) * 4, gp);
            }
        } else {
            // B tile: 32 k-rows x 128 floats -> [BK][BLDN]
#pragma unroll
            for (int jj = 0; jj < 4; jj++) {
                const int idx = tid + jj * 256;
                const int kr = idx >> 5, c = idx & 31;
                const float* gp = &Bm[(long long)(k0 + kr) * N + colBase + c * 4];
                CP_ASYNC16(smB + buf * B_STAGE_B + (kr * BLDN + c * 4) * 4, gp);
            }
        }
        CP_COMMIT();
    };

    const int NIT = K / BK;
    load_tiles(0, 0);

    for (int it = 0; it < NIT; ++it) {
        const int buf = it & 1;
        if (it + 1 < NIT) {
            load_tiles((it + 1) * BK, buf ^ 1);
            CP_WAIT(1);
        } else {
            CP_WAIT(0);
        }
        __syncthreads();

        const uint32_t* As = sA32 + buf * (A_STAGE_B / 4);
        const uint32_t* Bs = sB32 + buf * (B_STAGE_B / 4);

#pragma unroll
        for (int kk = 0; kk < 4; kk++) {
            const int kb = kk * 8;
            uint32_t afr[4][4];
#pragma unroll
            for (int i = 0; i < 4; i++) {
                const int r = wm * 64 + i * 16;
                afr[i][0] = As[(r + gid) * ALD + kb + tig];
                afr[i][1] = As[(r + gid + 8) * ALD + kb + tig];
                afr[i][2] = As[(r + gid) * ALD + kb + tig + 4];
                afr[i][3] = As[(r + gid + 8) * ALD + kb + tig + 4];
            }
            uint32_t bfr[4][2];
#pragma unroll
            for (int j = 0; j < 4; j++) {
                const int n = wn * 32 + j * 8 + gid;
                if (TRANSB) {
                    bfr[j][0] = Bs[n * BLDT + kb + tig];
                    bfr[j][1] = Bs[n * BLDT + kb + tig + 4];
                } else {
                    bfr[j][0] = Bs[(kb + tig) * BLDN + n];
                    bfr[j][1] = Bs[(kb + tig + 4) * BLDN + n];
                }
            }
#pragma unroll
            for (int i = 0; i < 4; i++)
#pragma unroll
                for (int j = 0; j < 4; j++)
                    mma_tf32(acc[i][j], afr[i], bfr[j]);
        }
        __syncthreads();
    }

    // ---- epilogue ----
#pragma unroll
    for (int i = 0; i < 4; i++) {
#pragma unroll
        for (int half = 0; half < 2; half++) {
            const long long r = rowBase + wm * 64 + i * 16 + gid + half * 8;
#pragma unroll
            for (int j = 0; j < 4; j++) {
                const int col = colBase + wn * 32 + j * 8 + tig * 2;
                float2 o;
                o.x = alpha * acc[i][j][half * 2 + 0];
                o.y = alpha * acc[i][j][half * 2 + 1];
                if (bias != nullptr) { o.x += bias[col]; o.y += bias[col + 1]; }
                if (ROUND) { o.x = round_tf32(o.x); o.y = round_tf32(o.y); }
                *(float2*)&C[r * N + col] = o;
            }
        }
    }
}

// ---------------- round-to-tf32 conversion ----------------
__global__ __launch_bounds__(256) void round_kernel(const float* __restrict__ in,
                                                    float* __restrict__ out, int n4)
{
    int i = blockIdx.x * blockDim.x + threadIdx.x;
    if (i < n4) {
        float4 v = ((const float4*)in)[i];
        v.x = round_tf32(v.x); v.y = round_tf32(v.y);
        v.z = round_tf32(v.z); v.w = round_tf32(v.w);
        ((float4*)out)[i] = v;
    }
}

// ---------------- row softmax (in place, rounds output to tf32) ----------------
__global__ __launch_bounds__(256) void softmax_kernel(float* __restrict__ S)
{
    float* row = S + (long long)blockIdx.x * SEQ;
    const int tid = threadIdx.x;

    float v[8];
    float m = -INFINITY;
#pragma unroll
    for (int i = 0; i < 8; i++) { v[i] = row[tid + i * 256]; m = fmaxf(m, v[i]); }

    __shared__ float red[256];
    red[tid] = m;
    __syncthreads();
#pragma unroll
    for (int s = 128; s > 0; s >>= 1) {
        if (tid < s) red[tid] = fmaxf(red[tid], red[tid + s]);
        __syncthreads();
    }
    m = red[0];
    __syncthreads();

    float sum = 0.0f;
#pragma unroll
    for (int i = 0; i < 8; i++) { v[i] = __expf(v[i] - m); sum += v[i]; }
    red[tid] = sum;
    __syncthreads();
#pragma unroll
    for (int s = 128; s > 0; s >>= 1) {
        if (tid < s) red[tid] += red[tid + s];
        __syncthreads();
    }
    const float inv = 1.0f / red[0];
#pragma unroll
    for (int i = 0; i < 8; i++)
        row[tid + i * 256] = round_tf32(v[i] * inv);
}

// ---------------- launch ----------------
extern "C" void kernel_launch(void* const* d_in, const int* in_sizes, int n_in,
                              void* d_out, int out_size)
{
    const float* x  = (const float*)d_in[0];
    const float* Wq = (const float*)d_in[1];
    const float* bq = (const float*)d_in[2];
    const float* Wk = (const float*)d_in[3];
    const float* bk = (const float*)d_in[4];
    const float* Wv = (const float*)d_in[5];
    const float* bv = (const float*)d_in[6];
    float* out = (float*)d_out;

    float *Q, *K_, *V, *Sc, *Wr;
    cudaGetSymbolAddress((void**)&Q,  g_Q);
    cudaGetSymbolAddress((void**)&K_, g_K);
    cudaGetSymbolAddress((void**)&V,  g_V);
    cudaGetSymbolAddress((void**)&Sc, g_S);
    cudaGetSymbolAddress((void**)&Wr, g_Wr);
    float* Xr  = Sc;                      // rounded x lives in g_S until scores GEMM
    float* Wqr = Wr;
    float* Wkr = Wr + (size_t)EMB * DIM;
    float* Wvr = Wr + 2 * (size_t)EMB * DIM;

    cudaFuncSetAttribute(mma_gemm<true,  true >, cudaFuncAttributeMaxDynamicSharedMemorySize, SMEM_SIZE);
    cudaFuncSetAttribute(mma_gemm<true,  false>, cudaFuncAttributeMaxDynamicSharedMemorySize, SMEM_SIZE);
    cudaFuncSetAttribute(mma_gemm<false, false>, cudaFuncAttributeMaxDynamicSharedMemorySize, SMEM_SIZE);

    const int Mq = BATCH * SEQ;           // 8192

    // round operands to tf32 (zero-mean rounding instead of HW truncation bias)
    {
        int n4x = Mq * DIM / 4;
        round_kernel<<<(n4x + 255) / 256, 256>>>(x, Xr, n4x);
        int n4w = EMB * DIM / 4;
        round_kernel<<<(n4w + 255) / 256, 256>>>(Wq, Wqr, n4w);
        round_kernel<<<(n4w + 255) / 256, 256>>>(Wk, Wkr, n4w);
        round_kernel<<<(n4w + 255) / 256, 256>>>(Wv, Wvr, n4w);
    }

    // QKV projections (outputs rounded to tf32 for downstream MMAs)
    {
        dim3 grid(EMB / BN, Mq / BM, 1);
        mma_gemm<true, true><<<grid, 256, SMEM_SIZE>>>(Xr, Wqr, bq, Q,  Mq, EMB, DIM, 1.0f, 0, 0, 0);
        mma_gemm<true, true><<<grid, 256, SMEM_SIZE>>>(Xr, Wkr, bk, K_, Mq, EMB, DIM, 1.0f, 0, 0, 0);
        mma_gemm<true, true><<<grid, 256, SMEM_SIZE>>>(Xr, Wvr, bv, V,  Mq, EMB, DIM, 1.0f, 0, 0, 0);
    }

    // scores = Q @ K^T / 32  (fp32 out; softmax rounds)
    {
        dim3 grid(SEQ / BN, SEQ / BM, BATCH);
        mma_gemm<true, false><<<grid, 256, SMEM_SIZE>>>(
            Q, K_, nullptr, Sc, SEQ, SEQ, EMB, 0.03125f,
            (long long)SEQ * EMB, (long long)SEQ * EMB, (long long)SEQ * SEQ);
    }

    softmax_kernel<<<BATCH * SEQ, 256>>>(Sc);

    // out = attn @ V
    {
        dim3 grid(EMB / BN, SEQ / BM, BATCH);
        mma_gemm<false, false><<<grid, 256, SMEM_SIZE>>>(
            Sc, V, nullptr, out, SEQ, EMB, SEQ, 1.0f,
            (long long)SEQ * SEQ, (long long)SEQ * EMB, (long long)SEQ * EMB);
    }
}